// round 2
// baseline (speedup 1.0000x reference)
#include <cuda_runtime.h>

#define N_ROWS  262144
#define NBINS   50
#define DCOL    512
#define D2      256          // float2 columns per row
#define NPART   148          // accumulate grid size (one CTA per SM)
#define NGROUPS (N_ROWS / 8) // 8-row groups; divides exactly

// -------- device scratch (no runtime allocation allowed) --------
__device__ __align__(16) int g_lab32[N_ROWS];      // 1 MB
__device__ float4 g_part[NPART][NBINS * D2];       // ~30 MB partial {s0,q0,s1,q1}
__device__ int    g_pcnt[NPART][NBINS];            // partial counts

// -------- kernel 1: copy + range-clamp labels (input is int32; see JAX x64 note) --------
__global__ void lab_convert(const int* __restrict__ lab) {
    int i = blockIdx.x * blockDim.x + threadIdx.x;
    if (i < N_ROWS) {
        int v = lab[i];
        v = v < 0 ? 0 : (v >= NBINS ? NBINS - 1 : v);   // safety clamp only
        g_lab32[i] = v;
    }
}

// -------- kernel 2: per-CTA private SMEM histogram of sum/sumsq --------
extern __shared__ unsigned char smem_raw[];

__global__ void __launch_bounds__(256, 1) accum_kernel(const float* __restrict__ feats) {
    float4* sacc = (float4*)smem_raw;              // [NBINS*D2] {s0,q0,s1,q1}
    int*    scnt = (int*)(sacc + NBINS * D2);      // [NBINS]
    const int tid = threadIdx.x;

    #pragma unroll 4
    for (int i = tid; i < NBINS * D2; i += 256) sacc[i] = make_float4(0.f, 0.f, 0.f, 0.f);
    if (tid < NBINS) scnt[tid] = 0;
    __syncthreads();

    const float2* __restrict__ f2 = (const float2*)feats;
    const int4*   __restrict__ lp = (const int4*)g_lab32;

    for (int g = blockIdx.x; g < NGROUPS; g += gridDim.x) {
        const int base = g * 8;
        // 8 labels via 2 broadcast 16B loads
        int4 L0 = lp[g * 2 + 0];
        int4 L1 = lp[g * 2 + 1];
        int labs[8] = {L0.x, L0.y, L0.z, L0.w, L1.x, L1.y, L1.z, L1.w};

        float2 v[8];
        #pragma unroll
        for (int u = 0; u < 8; u++)
            v[u] = f2[(size_t)(base + u) * D2 + tid];

        // per-block counts (deterministic integer atomics, 8 lanes only)
        if (tid < 8) atomicAdd(&scnt[labs[tid]], 1);

        // race-free RMW: thread owns columns 2*tid, 2*tid+1 exclusively
        #pragma unroll
        for (int u = 0; u < 8; u++) {
            int off = labs[u] * D2 + tid;
            float4 a = sacc[off];
            a.x += v[u].x; a.y = fmaf(v[u].x, v[u].x, a.y);
            a.z += v[u].y; a.w = fmaf(v[u].y, v[u].y, a.w);
            sacc[off] = a;
        }
    }
    __syncthreads();

    // flush partials (plain stores, fully overwritten every launch)
    #pragma unroll 4
    for (int i = tid; i < NBINS * D2; i += 256) g_part[blockIdx.x][i] = sacc[i];
    if (tid < NBINS) g_pcnt[blockIdx.x][tid] = scnt[tid];
}

// -------- kernel 3: reduce partials, EMA update, write new_mean/new_var/new_num --------
__global__ void finalize_kernel(const float* __restrict__ rmean,
                                const float* __restrict__ rvar,
                                const float* __restrict__ nst,
                                float* __restrict__ out) {
    const int idx = blockIdx.x * blockDim.x + threadIdx.x;   // 0 .. NBINS*D2-1

    if (idx < NBINS) {
        float c = 0.f;
        for (int b = 0; b < NPART; b++) c += (float)g_pcnt[b][idx];
        out[2 * NBINS * DCOL + idx] = nst[idx] + c;          // new_num
    }
    if (idx >= NBINS * D2) return;

    const int bin = idx / D2;
    const int t   = idx - bin * D2;

    float cnt = 0.f;
    for (int b = 0; b < NPART; b++) cnt += (float)g_pcnt[b][bin];

    float4 acc = make_float4(0.f, 0.f, 0.f, 0.f);
    for (int b = 0; b < NPART; b++) {
        float4 p = g_part[b][idx];
        acc.x += p.x; acc.y += p.y; acc.z += p.z; acc.w += p.w;
    }

    const float safe_n = fmaxf(cnt, 1.f);
    const float dn     = fmaxf(cnt - 1.f, 1.f);
    const float m0 = acc.x / safe_n;
    const float v0 = (acc.y - safe_n * m0 * m0) / dn;
    const float m1 = acc.z / safe_n;
    const float v1 = (acc.w - safe_n * m1 * m1) / dn;

    const int c0 = bin * DCOL + 2 * t;
    const float rm0 = rmean[c0], rm1 = rmean[c0 + 1];
    const float rv0 = rvar[c0],  rv1 = rvar[c0 + 1];
    const bool present = cnt > 0.f;

    const float f = 0.9f, g1 = 0.1f;
    float nm0 = present ? g1 * m0 + f * rm0 : rm0;
    float nm1 = present ? g1 * m1 + f * rm1 : rm1;
    float nv0 = present ? g1 * v0 + f * rv0 : rv0;
    float nv1 = present ? g1 * v1 + f * rv1 : rv1;

    ((float2*)out)[c0 / 2]                  = make_float2(nm0, nm1);  // new_mean
    ((float2*)(out + NBINS * DCOL))[c0 / 2] = make_float2(nv0, nv1);  // new_var
}

// -------- kernel 4: 5-tap reflect-101 smoothing over the bin axis --------
__global__ void smooth_kernel(const float* __restrict__ w, float* __restrict__ out) {
    const int idx = blockIdx.x * blockDim.x + threadIdx.x;   // 0 .. NBINS*DCOL-1
    if (idx >= NBINS * DCOL) return;
    const int bin = idx / DCOL;
    const int c   = idx - bin * DCOL;

    const float wk[5] = {w[0], w[1], w[2], w[3], w[4]};
    float sm = 0.f, sv = 0.f;
    #pragma unroll
    for (int k = 0; k < 5; k++) {
        int m = bin + k - 2;
        if (m < 0)       m = -m;                  // reflect101 left
        if (m >= NBINS)  m = 2 * (NBINS - 1) - m; // reflect101 right
        sm = fmaf(wk[k], out[m * DCOL + c], sm);
        sv = fmaf(wk[k], out[NBINS * DCOL + m * DCOL + c], sv);
    }
    const int base = 2 * NBINS * DCOL + NBINS;    // 51250
    out[base + idx]                = sm;          // smoothed_mean
    out[base + NBINS * DCOL + idx] = sv;          // smoothed_var
}

// -------- launch --------
extern "C" void kernel_launch(void* const* d_in, const int* in_sizes, int n_in,
                              void* d_out, int out_size) {
    const float* feats  = (const float*)d_in[0];
    const int*   labels = (const int*)d_in[1];
    const float* rmean  = (const float*)d_in[2];
    const float* rvar   = (const float*)d_in[3];
    const float* nst    = (const float*)d_in[4];
    const float* kw     = (const float*)d_in[5];
    float*       out    = (float*)d_out;

    const size_t smem = (size_t)NBINS * D2 * sizeof(float4) + NBINS * sizeof(int); // 205000 B
    cudaFuncSetAttribute(accum_kernel, cudaFuncAttributeMaxDynamicSharedMemorySize, (int)smem);

    lab_convert<<<(N_ROWS + 255) / 256, 256>>>(labels);
    accum_kernel<<<NPART, 256, smem>>>(feats);
    finalize_kernel<<<(NBINS * D2 + 255) / 256, 256>>>(rmean, rvar, nst, out);
    smooth_kernel<<<(NBINS * DCOL + 255) / 256, 256>>>(kw, out);
}

// round 3
// speedup vs baseline: 1.0542x; 1.0542x over previous
#include <cuda_runtime.h>

#define N_ROWS  262144
#define NBINS   50
#define DCOL    512
#define D2      256           // float2 columns per row
#define NPART   148           // accumulate grid size (one CTA per SM)
#define RPG     16            // rows per group
#define NGROUPS (N_ROWS / RPG) // 16384; divides exactly

// -------- device scratch (no runtime allocation allowed) --------
__device__ __align__(16) int g_lab32[N_ROWS];      // 1 MB
__device__ float4 g_part[NPART][NBINS * D2];       // ~30 MB partial {s0,q0,s1,q1}
__device__ int    g_pcnt[NPART][NBINS];            // partial counts

// -------- kernel 1: copy + range-clamp labels (input arrives as int32) --------
__global__ void lab_convert(const int* __restrict__ lab) {
    int i = blockIdx.x * blockDim.x + threadIdx.x;
    if (i < N_ROWS) {
        int v = lab[i];
        v = v < 0 ? 0 : (v >= NBINS ? NBINS - 1 : v);   // safety clamp only
        g_lab32[i] = v;
    }
}

// -------- kernel 2: per-CTA private SMEM histogram of sum/sumsq --------
extern __shared__ unsigned char smem_raw[];

__global__ void __launch_bounds__(256, 1) accum_kernel(const float* __restrict__ feats) {
    float4* sacc = (float4*)smem_raw;              // [NBINS*D2] {s0,q0,s1,q1}
    int*    scnt = (int*)(sacc + NBINS * D2);      // [NBINS]
    const int tid = threadIdx.x;

    #pragma unroll 4
    for (int i = tid; i < NBINS * D2; i += 256) sacc[i] = make_float4(0.f, 0.f, 0.f, 0.f);
    if (tid < NBINS) scnt[tid] = 0;
    __syncthreads();

    const float2* __restrict__ f2 = (const float2*)feats;
    const int4*   __restrict__ lp = (const int4*)g_lab32;

    for (int g = blockIdx.x; g < NGROUPS; g += gridDim.x) {
        const int base = g * RPG;

        // 16 labels via 4 broadcast 16B loads
        int labs[RPG];
        #pragma unroll
        for (int q = 0; q < RPG / 4; q++) {
            int4 L = lp[g * (RPG / 4) + q];
            labs[q * 4 + 0] = L.x; labs[q * 4 + 1] = L.y;
            labs[q * 4 + 2] = L.z; labs[q * 4 + 3] = L.w;
        }

        // 16 row-loads in flight (32 KB/SM across 8 warps)
        float2 v[RPG];
        #pragma unroll
        for (int u = 0; u < RPG; u++)
            v[u] = f2[(size_t)(base + u) * D2 + tid];

        // per-block counts (deterministic integer atomics, 16 lanes only)
        if (tid < RPG) atomicAdd(&scnt[labs[tid]], 1);

        // race-free RMW: thread owns columns 2*tid, 2*tid+1 exclusively
        #pragma unroll
        for (int u = 0; u < RPG; u++) {
            int off = labs[u] * D2 + tid;
            float4 a = sacc[off];
            a.x += v[u].x; a.y = fmaf(v[u].x, v[u].x, a.y);
            a.z += v[u].y; a.w = fmaf(v[u].y, v[u].y, a.w);
            sacc[off] = a;
        }
    }
    __syncthreads();

    // flush partials (plain stores, fully overwritten every launch)
    #pragma unroll 4
    for (int i = tid; i < NBINS * D2; i += 256) g_part[blockIdx.x][i] = sacc[i];
    if (tid < NBINS) g_pcnt[blockIdx.x][tid] = scnt[tid];
}

// -------- kernel 3: reduce partials, EMA update, write new_mean/new_var/new_num --------
__global__ void finalize_kernel(const float* __restrict__ rmean,
                                const float* __restrict__ rvar,
                                const float* __restrict__ nst,
                                float* __restrict__ out) {
    const int idx = blockIdx.x * blockDim.x + threadIdx.x;   // 0 .. NBINS*D2-1

    if (idx < NBINS) {
        float c = 0.f;
        for (int b = 0; b < NPART; b++) c += (float)g_pcnt[b][idx];
        out[2 * NBINS * DCOL + idx] = nst[idx] + c;          // new_num
    }
    if (idx >= NBINS * D2) return;

    const int bin = idx / D2;
    const int t   = idx - bin * D2;

    float cnt = 0.f;
    for (int b = 0; b < NPART; b++) cnt += (float)g_pcnt[b][bin];

    float4 acc = make_float4(0.f, 0.f, 0.f, 0.f);
    for (int b = 0; b < NPART; b++) {
        float4 p = g_part[b][idx];
        acc.x += p.x; acc.y += p.y; acc.z += p.z; acc.w += p.w;
    }

    const float safe_n = fmaxf(cnt, 1.f);
    const float dn     = fmaxf(cnt - 1.f, 1.f);
    const float m0 = acc.x / safe_n;
    const float v0 = (acc.y - safe_n * m0 * m0) / dn;
    const float m1 = acc.z / safe_n;
    const float v1 = (acc.w - safe_n * m1 * m1) / dn;

    const int c0 = bin * DCOL + 2 * t;
    const float rm0 = rmean[c0], rm1 = rmean[c0 + 1];
    const float rv0 = rvar[c0],  rv1 = rvar[c0 + 1];
    const bool present = cnt > 0.f;

    const float f = 0.9f, g1 = 0.1f;
    float nm0 = present ? g1 * m0 + f * rm0 : rm0;
    float nm1 = present ? g1 * m1 + f * rm1 : rm1;
    float nv0 = present ? g1 * v0 + f * rv0 : rv0;
    float nv1 = present ? g1 * v1 + f * rv1 : rv1;

    ((float2*)out)[c0 / 2]                  = make_float2(nm0, nm1);  // new_mean
    ((float2*)(out + NBINS * DCOL))[c0 / 2] = make_float2(nv0, nv1);  // new_var
}

// -------- kernel 4: 5-tap reflect-101 smoothing over the bin axis --------
__global__ void smooth_kernel(const float* __restrict__ w, float* __restrict__ out) {
    const int idx = blockIdx.x * blockDim.x + threadIdx.x;   // 0 .. NBINS*DCOL-1
    if (idx >= NBINS * DCOL) return;
    const int bin = idx / DCOL;
    const int c   = idx - bin * DCOL;

    const float wk[5] = {w[0], w[1], w[2], w[3], w[4]};
    float sm = 0.f, sv = 0.f;
    #pragma unroll
    for (int k = 0; k < 5; k++) {
        int m = bin + k - 2;
        if (m < 0)       m = -m;                  // reflect101 left
        if (m >= NBINS)  m = 2 * (NBINS - 1) - m; // reflect101 right
        sm = fmaf(wk[k], out[m * DCOL + c], sm);
        sv = fmaf(wk[k], out[NBINS * DCOL + m * DCOL + c], sv);
    }
    const int base = 2 * NBINS * DCOL + NBINS;    // 51250
    out[base + idx]                = sm;          // smoothed_mean
    out[base + NBINS * DCOL + idx] = sv;          // smoothed_var
}

// -------- launch --------
extern "C" void kernel_launch(void* const* d_in, const int* in_sizes, int n_in,
                              void* d_out, int out_size) {
    const float* feats  = (const float*)d_in[0];
    const int*   labels = (const int*)d_in[1];
    const float* rmean  = (const float*)d_in[2];
    const float* rvar   = (const float*)d_in[3];
    const float* nst    = (const float*)d_in[4];
    const float* kw     = (const float*)d_in[5];
    float*       out    = (float*)d_out;

    const size_t smem = (size_t)NBINS * D2 * sizeof(float4) + NBINS * sizeof(int); // 205000 B
    cudaFuncSetAttribute(accum_kernel, cudaFuncAttributeMaxDynamicSharedMemorySize, (int)smem);

    lab_convert<<<(N_ROWS + 255) / 256, 256>>>(labels);
    accum_kernel<<<NPART, 256, smem>>>(feats);
    finalize_kernel<<<(NBINS * D2 + 255) / 256, 256>>>(rmean, rvar, nst, out);
    smooth_kernel<<<(NBINS * DCOL + 255) / 256, 256>>>(kw, out);
}

// round 4
// speedup vs baseline: 1.6587x; 1.5735x over previous
#include <cuda_runtime.h>

#define N_ROWS  262144
#define NBINS   50
#define DCOL    512
#define D2      256            // float2 columns per row
#define NPART   148            // accumulate grid size (one CTA per SM)
#define RPG     16             // rows per group
#define NGROUPS (N_ROWS / RPG) // 16384
#define NSEG    8              // reduction segments

// -------- device scratch --------
__device__ float4 g_part [NPART][NBINS * D2];   // ~30 MB partials {s0,q0,s1,q1}
__device__ float4 g_part2[NSEG ][NBINS * D2];   // stage-2 partials
__device__ int    g_pcnt [NPART][NBINS];        // partial counts

__device__ __forceinline__ int clampbin(int v) {
    return v < 0 ? 0 : (v >= NBINS ? NBINS - 1 : v);
}

// -------- kernel 1: pipelined per-CTA SMEM histogram of sum/sumsq --------
extern __shared__ unsigned char smem_raw[];

__global__ void __launch_bounds__(256, 1) accum_kernel(const float* __restrict__ feats,
                                                       const int* __restrict__ labels) {
    float4* sacc = (float4*)smem_raw;              // [NBINS*D2]
    int*    scnt = (int*)(sacc + NBINS * D2);      // [NBINS]
    const int tid = threadIdx.x;

    #pragma unroll 4
    for (int i = tid; i < NBINS * D2; i += 256) sacc[i] = make_float4(0.f, 0.f, 0.f, 0.f);
    if (tid < NBINS) scnt[tid] = 0;
    __syncthreads();

    const float2* __restrict__ f2 = (const float2*)feats;
    const int4*   __restrict__ lp = (const int4*)labels;

    int g = blockIdx.x;
    float2 vc[RPG];
    int4   Lc[RPG / 4];

    // prologue: load first group
    #pragma unroll
    for (int q = 0; q < RPG / 4; q++) Lc[q] = lp[g * (RPG / 4) + q];
    #pragma unroll
    for (int u = 0; u < RPG; u++) vc[u] = f2[(size_t)(g * RPG + u) * D2 + tid];

    for (; g < NGROUPS; g += NPART) {
        const int gn = g + NPART;
        float2 vn[RPG];
        int4   Ln[RPG / 4];
        if (gn < NGROUPS) {
            // prefetch next group: independent LDGs in flight during RMW below
            #pragma unroll
            for (int q = 0; q < RPG / 4; q++) Ln[q] = lp[gn * (RPG / 4) + q];
            #pragma unroll
            for (int u = 0; u < RPG; u++) vn[u] = f2[(size_t)(gn * RPG + u) * D2 + tid];
        }

        // per-block counts: direct GMEM read (L1 hit), no dynamic reg indexing
        if (tid < RPG) atomicAdd(&scnt[clampbin(labels[g * RPG + tid])], 1);

        int labs[RPG] = {clampbin(Lc[0].x), clampbin(Lc[0].y), clampbin(Lc[0].z), clampbin(Lc[0].w),
                         clampbin(Lc[1].x), clampbin(Lc[1].y), clampbin(Lc[1].z), clampbin(Lc[1].w),
                         clampbin(Lc[2].x), clampbin(Lc[2].y), clampbin(Lc[2].z), clampbin(Lc[2].w),
                         clampbin(Lc[3].x), clampbin(Lc[3].y), clampbin(Lc[3].z), clampbin(Lc[3].w)};

        // race-free RMW: thread owns float columns 2*tid, 2*tid+1 exclusively
        #pragma unroll
        for (int u = 0; u < RPG; u++) {
            const int off = labs[u] * D2 + tid;
            float4 a = sacc[off];
            a.x += vc[u].x; a.y = fmaf(vc[u].x, vc[u].x, a.y);
            a.z += vc[u].y; a.w = fmaf(vc[u].y, vc[u].y, a.w);
            sacc[off] = a;
        }

        #pragma unroll
        for (int q = 0; q < RPG / 4; q++) Lc[q] = Ln[q];
        #pragma unroll
        for (int u = 0; u < RPG; u++) vc[u] = vn[u];
    }
    __syncthreads();

    // flush partials (plain stores; fully overwritten every launch)
    #pragma unroll 4
    for (int i = tid; i < NBINS * D2; i += 256) g_part[blockIdx.x][i] = sacc[i];
    if (tid < NBINS) g_pcnt[blockIdx.x][tid] = scnt[tid];
}

// -------- kernel 2: stage-1 partial reduction (148 -> 8 segments) --------
__global__ void reduce_part() {
    const int i = blockIdx.x * blockDim.x + threadIdx.x;   // 0 .. NSEG*12800-1
    if (i >= NSEG * NBINS * D2) return;
    const int seg = i / (NBINS * D2);
    const int e   = i - seg * (NBINS * D2);
    // 148 = 8*18 + 4 : first 4 segments take 19, rest 18
    const int b0  = seg * 18 + (seg < 4 ? seg : 4);
    const int len = 18 + (seg < 4 ? 1 : 0);
    float4 acc = make_float4(0.f, 0.f, 0.f, 0.f);
    for (int b = b0; b < b0 + len; b++) {
        float4 p = g_part[b][e];
        acc.x += p.x; acc.y += p.y; acc.z += p.z; acc.w += p.w;
    }
    g_part2[seg][e] = acc;
}

// -------- kernel 3: combine segments, EMA update, write new_mean/new_var/new_num ----
__global__ void finalize_kernel(const float* __restrict__ rmean,
                                const float* __restrict__ rvar,
                                const float* __restrict__ nst,
                                float* __restrict__ out) {
    const int idx = blockIdx.x * blockDim.x + threadIdx.x;   // 0 .. NBINS*D2-1

    if (idx < NBINS) {
        float c = 0.f;
        for (int b = 0; b < NPART; b++) c += (float)g_pcnt[b][idx];
        out[2 * NBINS * DCOL + idx] = nst[idx] + c;          // new_num
    }
    if (idx >= NBINS * D2) return;

    const int bin = idx / D2;
    const int t   = idx - bin * D2;

    float cnt = 0.f;
    for (int b = 0; b < NPART; b++) cnt += (float)g_pcnt[b][bin];

    float4 acc = make_float4(0.f, 0.f, 0.f, 0.f);
    #pragma unroll
    for (int s = 0; s < NSEG; s++) {
        float4 p = g_part2[s][idx];
        acc.x += p.x; acc.y += p.y; acc.z += p.z; acc.w += p.w;
    }

    const float safe_n = fmaxf(cnt, 1.f);
    const float dn     = fmaxf(cnt - 1.f, 1.f);
    const float m0 = acc.x / safe_n;
    const float v0 = (acc.y - safe_n * m0 * m0) / dn;
    const float m1 = acc.z / safe_n;
    const float v1 = (acc.w - safe_n * m1 * m1) / dn;

    const int c0 = bin * DCOL + 2 * t;
    const float rm0 = rmean[c0], rm1 = rmean[c0 + 1];
    const float rv0 = rvar[c0],  rv1 = rvar[c0 + 1];
    const bool present = cnt > 0.f;

    const float f = 0.9f, g1 = 0.1f;
    float nm0 = present ? g1 * m0 + f * rm0 : rm0;
    float nm1 = present ? g1 * m1 + f * rm1 : rm1;
    float nv0 = present ? g1 * v0 + f * rv0 : rv0;
    float nv1 = present ? g1 * v1 + f * rv1 : rv1;

    ((float2*)out)[c0 / 2]                  = make_float2(nm0, nm1);  // new_mean
    ((float2*)(out + NBINS * DCOL))[c0 / 2] = make_float2(nv0, nv1);  // new_var
}

// -------- kernel 4: 5-tap reflect-101 smoothing over the bin axis --------
__global__ void smooth_kernel(const float* __restrict__ w, float* __restrict__ out) {
    const int idx = blockIdx.x * blockDim.x + threadIdx.x;   // 0 .. NBINS*DCOL-1
    if (idx >= NBINS * DCOL) return;
    const int bin = idx / DCOL;
    const int c   = idx - bin * DCOL;

    const float wk[5] = {w[0], w[1], w[2], w[3], w[4]};
    float sm = 0.f, sv = 0.f;
    #pragma unroll
    for (int k = 0; k < 5; k++) {
        int m = bin + k - 2;
        if (m < 0)       m = -m;                  // reflect101 left
        if (m >= NBINS)  m = 2 * (NBINS - 1) - m; // reflect101 right
        sm = fmaf(wk[k], out[m * DCOL + c], sm);
        sv = fmaf(wk[k], out[NBINS * DCOL + m * DCOL + c], sv);
    }
    const int base = 2 * NBINS * DCOL + NBINS;    // 51250
    out[base + idx]                = sm;          // smoothed_mean
    out[base + NBINS * DCOL + idx] = sv;          // smoothed_var
}

// -------- launch --------
extern "C" void kernel_launch(void* const* d_in, const int* in_sizes, int n_in,
                              void* d_out, int out_size) {
    const float* feats  = (const float*)d_in[0];
    const int*   labels = (const int*)d_in[1];
    const float* rmean  = (const float*)d_in[2];
    const float* rvar   = (const float*)d_in[3];
    const float* nst    = (const float*)d_in[4];
    const float* kw     = (const float*)d_in[5];
    float*       out    = (float*)d_out;

    const size_t smem = (size_t)NBINS * D2 * sizeof(float4) + NBINS * sizeof(int); // 205000 B
    cudaFuncSetAttribute(accum_kernel, cudaFuncAttributeMaxDynamicSharedMemorySize, (int)smem);

    accum_kernel<<<NPART, 256, smem>>>(feats, labels);
    reduce_part<<<(NSEG * NBINS * D2 + 255) / 256, 256>>>();
    finalize_kernel<<<(NBINS * D2 + 255) / 256, 256>>>(rmean, rvar, nst, out);
    smooth_kernel<<<(NBINS * DCOL + 255) / 256, 256>>>(kw, out);
}

// round 8
// speedup vs baseline: 1.8240x; 1.0996x over previous
#include <cuda_runtime.h>

#define N_ROWS  262144
#define NBINS   50
#define DCOL    512
#define HCOL    256            // columns per half-CTA
#define NPAIR   148            // row-partition pairs
#define NCTA    (2 * NPAIR)    // 296 CTAs, 2 per SM
#define RPG     16             // rows per group
#define NGROUPS (N_ROWS / RPG) // 16384
#define NSEG    4              // reduction segments (148 pairs / 4 = 37)

// -------- device scratch --------
__device__ float2 g_part [NCTA][NBINS * HCOL];   // ~30 MB partials {s,q}
__device__ float2 g_part2[NSEG][NBINS * DCOL];   // 800 KB stage-2 partials
__device__ int    g_pcnt [NPAIR][NBINS];         // per-pair counts

__device__ __forceinline__ int clampbin(int v) {
    return v < 0 ? 0 : (v >= NBINS ? NBINS - 1 : v);
}

// -------- kernel 1: pipelined per-CTA SMEM histogram (column-split, 2 CTAs/SM) ----
extern __shared__ unsigned char smem_raw[];

__global__ void __launch_bounds__(256, 2) accum_kernel(const float* __restrict__ feats,
                                                       const int* __restrict__ labels) {
    float2* sacc = (float2*)smem_raw;              // [NBINS*HCOL] {sum, sumsq}
    int*    scnt = (int*)(sacc + NBINS * HCOL);    // [NBINS]
    const int tid  = threadIdx.x;
    const int half = blockIdx.x & 1;               // which 256-column half
    const int pair = blockIdx.x >> 1;              // row partition

    #pragma unroll 4
    for (int i = tid; i < NBINS * HCOL; i += 256) sacc[i] = make_float2(0.f, 0.f);
    if (tid < NBINS) scnt[tid] = 0;
    __syncthreads();

    const float* __restrict__ fcol = feats + half * HCOL + tid;  // this thread's column
    const int4*  __restrict__ lp   = (const int4*)labels;

    int g = pair;
    float vc[RPG];
    int4  Lc[RPG / 4];

    // prologue
    #pragma unroll
    for (int q = 0; q < RPG / 4; q++) Lc[q] = lp[g * (RPG / 4) + q];
    #pragma unroll
    for (int u = 0; u < RPG; u++) vc[u] = fcol[(size_t)(g * RPG + u) * DCOL];

    for (; g < NGROUPS; g += NPAIR) {
        const int gn = g + NPAIR;
        float vn[RPG];
        int4  Ln[RPG / 4];
        if (gn < NGROUPS) {
            #pragma unroll
            for (int q = 0; q < RPG / 4; q++) Ln[q] = lp[gn * (RPG / 4) + q];
            #pragma unroll
            for (int u = 0; u < RPG; u++) vn[u] = fcol[(size_t)(gn * RPG + u) * DCOL];
        }

        // counts: only half 0 of each pair (deterministic, 16 lanes, L2-resident labels)
        if (half == 0 && tid < RPG) atomicAdd(&scnt[clampbin(labels[g * RPG + tid])], 1);

        int labs[RPG] = {clampbin(Lc[0].x), clampbin(Lc[0].y), clampbin(Lc[0].z), clampbin(Lc[0].w),
                         clampbin(Lc[1].x), clampbin(Lc[1].y), clampbin(Lc[1].z), clampbin(Lc[1].w),
                         clampbin(Lc[2].x), clampbin(Lc[2].y), clampbin(Lc[2].z), clampbin(Lc[2].w),
                         clampbin(Lc[3].x), clampbin(Lc[3].y), clampbin(Lc[3].z), clampbin(Lc[3].w)};

        // race-free RMW: thread owns exactly one float column
        #pragma unroll
        for (int u = 0; u < RPG; u++) {
            const int off = labs[u] * HCOL + tid;
            float2 a = sacc[off];
            a.x += vc[u];
            a.y = fmaf(vc[u], vc[u], a.y);
            sacc[off] = a;
        }

        #pragma unroll
        for (int q = 0; q < RPG / 4; q++) Lc[q] = Ln[q];
        #pragma unroll
        for (int u = 0; u < RPG; u++) vc[u] = vn[u];
    }
    __syncthreads();

    // flush partials
    #pragma unroll 4
    for (int i = tid; i < NBINS * HCOL; i += 256) g_part[blockIdx.x][i] = sacc[i];
    if (half == 0 && tid < NBINS) g_pcnt[pair][tid] = scnt[tid];
}

// -------- kernel 2: stage-1 reduction over pairs (296 partials -> 4 segments) -----
__global__ void reduce_part() {
    const int i = blockIdx.x * blockDim.x + threadIdx.x;   // 0 .. NSEG*25600-1
    if (i >= NSEG * NBINS * DCOL) return;
    const int seg = i / (NBINS * DCOL);
    const int e   = i - seg * (NBINS * DCOL);              // (bin, col) flattened
    const int bin = e / DCOL;
    const int col = e - bin * DCOL;
    const int h   = col >> 8;                              // which half CTA
    const int t   = col & (HCOL - 1);
    const int eo  = bin * HCOL + t;

    float2 acc = make_float2(0.f, 0.f);
    const int p0 = seg * (NPAIR / NSEG);                   // 37 pairs per segment
    for (int p = p0; p < p0 + NPAIR / NSEG; p++) {
        float2 v = g_part[2 * p + h][eo];
        acc.x += v.x; acc.y += v.y;
    }
    g_part2[seg][e] = acc;
}

// -------- kernel 3: combine segments, EMA update, write new_mean/new_var/new_num --
__global__ void finalize_kernel(const float* __restrict__ rmean,
                                const float* __restrict__ rvar,
                                const float* __restrict__ nst,
                                float* __restrict__ out) {
    const int idx = blockIdx.x * blockDim.x + threadIdx.x; // 0 .. NBINS*DCOL-1

    if (idx < NBINS) {
        float c = 0.f;
        for (int b = 0; b < NPAIR; b++) c += (float)g_pcnt[b][idx];
        out[2 * NBINS * DCOL + idx] = nst[idx] + c;        // new_num
    }
    if (idx >= NBINS * DCOL) return;

    const int bin = idx / DCOL;

    float cnt = 0.f;
    for (int b = 0; b < NPAIR; b++) cnt += (float)g_pcnt[b][bin];

    float2 acc = make_float2(0.f, 0.f);
    #pragma unroll
    for (int s = 0; s < NSEG; s++) {
        float2 p = g_part2[s][idx];
        acc.x += p.x; acc.y += p.y;
    }

    const float safe_n = fmaxf(cnt, 1.f);
    const float dn     = fmaxf(cnt - 1.f, 1.f);
    const float m = acc.x / safe_n;
    const float v = (acc.y - safe_n * m * m) / dn;

    const float rm = rmean[idx], rv = rvar[idx];
    const bool present = cnt > 0.f;
    const float f = 0.9f, g1 = 0.1f;

    out[idx]                = present ? g1 * m + f * rm : rm;  // new_mean
    out[NBINS * DCOL + idx] = present ? g1 * v + f * rv : rv;  // new_var
}

// -------- kernel 4: 5-tap reflect-101 smoothing over the bin axis --------
__global__ void smooth_kernel(const float* __restrict__ w, float* __restrict__ out) {
    const int idx = blockIdx.x * blockDim.x + threadIdx.x;   // 0 .. NBINS*DCOL-1
    if (idx >= NBINS * DCOL) return;
    const int bin = idx / DCOL;
    const int c   = idx - bin * DCOL;

    const float wk[5] = {w[0], w[1], w[2], w[3], w[4]};
    float sm = 0.f, sv = 0.f;
    #pragma unroll
    for (int k = 0; k < 5; k++) {
        int m = bin + k - 2;
        if (m < 0)       m = -m;                  // reflect101 left
        if (m >= NBINS)  m = 2 * (NBINS - 1) - m; // reflect101 right
        sm = fmaf(wk[k], out[m * DCOL + c], sm);
        sv = fmaf(wk[k], out[NBINS * DCOL + m * DCOL + c], sv);
    }
    const int base = 2 * NBINS * DCOL + NBINS;    // 51250
    out[base + idx]                = sm;          // smoothed_mean
    out[base + NBINS * DCOL + idx] = sv;          // smoothed_var
}

// -------- launch --------
extern "C" void kernel_launch(void* const* d_in, const int* in_sizes, int n_in,
                              void* d_out, int out_size) {
    const float* feats  = (const float*)d_in[0];
    const int*   labels = (const int*)d_in[1];
    const float* rmean  = (const float*)d_in[2];
    const float* rvar   = (const float*)d_in[3];
    const float* nst    = (const float*)d_in[4];
    const float* kw     = (const float*)d_in[5];
    float*       out    = (float*)d_out;

    const size_t smem = (size_t)NBINS * HCOL * sizeof(float2) + NBINS * sizeof(int); // 102600 B
    cudaFuncSetAttribute(accum_kernel, cudaFuncAttributeMaxDynamicSharedMemorySize, (int)smem);

    accum_kernel<<<NCTA, 256, smem>>>(feats, labels);
    reduce_part<<<(NSEG * NBINS * DCOL + 255) / 256, 256>>>();
    finalize_kernel<<<(NBINS * DCOL + 255) / 256, 256>>>(rmean, rvar, nst, out);
    smooth_kernel<<<(NBINS * DCOL + 255) / 256, 256>>>(kw, out);
}

// round 9
// speedup vs baseline: 2.0450x; 1.1212x over previous
#include <cuda_runtime.h>

#define N_ROWS  262144
#define NBINS   50
#define DCOL    512
#define D2      256             // float2 columns
#define NBLK    256             // sort blocks (1024 rows each)
#define ROWS_PB 1024
#define SCH     12              // chunks per bin
#define NACC    (NBINS * SCH)   // 600 accum CTAs

// -------- device scratch --------
__device__ int    g_bhist[NBLK][NBINS];    // per-block label histograms
__device__ int    g_gbase[NBLK][NBINS];    // per-block per-bin exclusive base
__device__ int    g_off[NBINS + 1];        // bin offsets (exclusive scan)
__device__ int    g_cnt[NBINS];            // bin totals
__device__ int    g_sorted[N_ROWS];        // row indices sorted by bin (stable)
__device__ float4 g_bpart[NACC][D2];       // per-CTA partials {s0,q0,s1,q1}

__device__ __forceinline__ int clampbin(int v) {
    return v < 0 ? 0 : (v >= NBINS ? NBINS - 1 : v);
}

// -------- K1: per-block label histograms --------
__global__ void hist_kernel(const int* __restrict__ labels) {
    __shared__ int h[NBINS];
    const int tid = threadIdx.x, blk = blockIdx.x;
    if (tid < NBINS) h[tid] = 0;
    __syncthreads();
    #pragma unroll
    for (int k = 0; k < 4; k++)
        atomicAdd(&h[clampbin(labels[blk * ROWS_PB + k * 256 + tid])], 1);
    __syncthreads();
    if (tid < NBINS) g_bhist[blk][tid] = h[tid];
}

// -------- K2: scan (per-bin block prefix + bin offsets) --------
__global__ void scan_kernel() {
    __shared__ int tot[NBINS];
    const int b = threadIdx.x;
    if (b < NBINS) {
        int run = 0;
        #pragma unroll 16
        for (int k = 0; k < NBLK; k++) {
            int h = g_bhist[k][b];
            g_gbase[k][b] = run;
            run += h;
        }
        tot[b] = run;
        g_cnt[b] = run;
    }
    __syncthreads();
    if (b == 0) {
        int off = 0;
        for (int i = 0; i < NBINS; i++) { g_off[i] = off; off += tot[i]; }
        g_off[NBINS] = off;
    }
}

// -------- K3: stable scatter (warp per block, deterministic) --------
__global__ void scatter_kernel(const int* __restrict__ labels) {
    __shared__ int cnt[NBINS];
    const int lane = threadIdx.x, blk = blockIdx.x;
    for (int i = lane; i < NBINS; i += 32)
        cnt[i] = g_off[i] + g_gbase[blk][i];
    __syncwarp();

    for (int t = 0; t < ROWS_PB / 32; t++) {
        const int r   = blk * ROWS_PB + t * 32 + lane;
        const int lab = clampbin(labels[r]);
        unsigned mask = __match_any_sync(0xFFFFFFFFu, lab);
        const int leader = __ffs(mask) - 1;
        const int rank   = __popc(mask & ((1u << lane) - 1u));
        int base = 0;
        if (lane == leader) {
            base = cnt[lab];
            cnt[lab] = base + __popc(mask);
        }
        base = __shfl_sync(0xFFFFFFFFu, base, leader);
        g_sorted[base + rank] = r;
        __syncwarp();
    }
}

// -------- K4: register-only accumulation, one bin per CTA --------
__global__ void __launch_bounds__(256) accum_kernel(const float* __restrict__ feats) {
    const int b   = blockIdx.x / SCH;
    const int j   = blockIdx.x % SCH;
    const int o0  = g_off[b];
    const int len = g_off[b + 1] - o0;
    const int p0  = o0 + (int)((long long)len * j / SCH);
    const int p1  = o0 + (int)((long long)len * (j + 1) / SCH);
    const int tid = threadIdx.x;

    const float2* __restrict__ f2 = (const float2*)feats;
    float s0 = 0.f, q0 = 0.f, s1 = 0.f, q1 = 0.f;

    int p = p0;
    for (; p + 8 <= p1; p += 8) {
        int idx[8];
        #pragma unroll
        for (int u = 0; u < 8; u++) idx[u] = g_sorted[p + u];
        float2 v[8];
        #pragma unroll
        for (int u = 0; u < 8; u++) v[u] = f2[(size_t)idx[u] * D2 + tid];
        #pragma unroll
        for (int u = 0; u < 8; u++) {
            s0 += v[u].x; q0 = fmaf(v[u].x, v[u].x, q0);
            s1 += v[u].y; q1 = fmaf(v[u].y, v[u].y, q1);
        }
    }
    for (; p < p1; p++) {
        float2 v = f2[(size_t)g_sorted[p] * D2 + tid];
        s0 += v.x; q0 = fmaf(v.x, v.x, q0);
        s1 += v.y; q1 = fmaf(v.y, v.y, q1);
    }
    g_bpart[blockIdx.x][tid] = make_float4(s0, q0, s1, q1);
}

// -------- K5: reduce partials, EMA update, write new_mean/new_var/new_num --------
__global__ void finalize_kernel(const float* __restrict__ rmean,
                                const float* __restrict__ rvar,
                                const float* __restrict__ nst,
                                float* __restrict__ out) {
    const int idx = blockIdx.x * blockDim.x + threadIdx.x;   // 0 .. NBINS*D2-1
    if (idx < NBINS)
        out[2 * NBINS * DCOL + idx] = nst[idx] + (float)g_cnt[idx];   // new_num
    if (idx >= NBINS * D2) return;

    const int b = idx / D2;
    const int c = idx - b * D2;

    float4 acc = make_float4(0.f, 0.f, 0.f, 0.f);
    #pragma unroll
    for (int j = 0; j < SCH; j++) {
        float4 p = g_bpart[b * SCH + j][c];
        acc.x += p.x; acc.y += p.y; acc.z += p.z; acc.w += p.w;
    }

    const float cnt    = (float)g_cnt[b];
    const float safe_n = fmaxf(cnt, 1.f);
    const float dn     = fmaxf(cnt - 1.f, 1.f);
    const float m0 = acc.x / safe_n;
    const float v0 = (acc.y - safe_n * m0 * m0) / dn;
    const float m1 = acc.z / safe_n;
    const float v1 = (acc.w - safe_n * m1 * m1) / dn;

    const int c0 = b * DCOL + 2 * c;
    const float rm0 = rmean[c0], rm1 = rmean[c0 + 1];
    const float rv0 = rvar[c0],  rv1 = rvar[c0 + 1];
    const bool present = cnt > 0.f;
    const float f = 0.9f, g1 = 0.1f;

    float nm0 = present ? g1 * m0 + f * rm0 : rm0;
    float nm1 = present ? g1 * m1 + f * rm1 : rm1;
    float nv0 = present ? g1 * v0 + f * rv0 : rv0;
    float nv1 = present ? g1 * v1 + f * rv1 : rv1;

    ((float2*)out)[c0 / 2]                  = make_float2(nm0, nm1);  // new_mean
    ((float2*)(out + NBINS * DCOL))[c0 / 2] = make_float2(nv0, nv1);  // new_var
}

// -------- K6: 5-tap reflect-101 smoothing over the bin axis --------
__global__ void smooth_kernel(const float* __restrict__ w, float* __restrict__ out) {
    const int idx = blockIdx.x * blockDim.x + threadIdx.x;   // 0 .. NBINS*DCOL-1
    if (idx >= NBINS * DCOL) return;
    const int bin = idx / DCOL;
    const int c   = idx - bin * DCOL;

    const float wk[5] = {w[0], w[1], w[2], w[3], w[4]};
    float sm = 0.f, sv = 0.f;
    #pragma unroll
    for (int k = 0; k < 5; k++) {
        int m = bin + k - 2;
        if (m < 0)       m = -m;                  // reflect101 left
        if (m >= NBINS)  m = 2 * (NBINS - 1) - m; // reflect101 right
        sm = fmaf(wk[k], out[m * DCOL + c], sm);
        sv = fmaf(wk[k], out[NBINS * DCOL + m * DCOL + c], sv);
    }
    const int base = 2 * NBINS * DCOL + NBINS;    // 51250
    out[base + idx]                = sm;          // smoothed_mean
    out[base + NBINS * DCOL + idx] = sv;          // smoothed_var
}

// -------- launch --------
extern "C" void kernel_launch(void* const* d_in, const int* in_sizes, int n_in,
                              void* d_out, int out_size) {
    const float* feats  = (const float*)d_in[0];
    const int*   labels = (const int*)d_in[1];
    const float* rmean  = (const float*)d_in[2];
    const float* rvar   = (const float*)d_in[3];
    const float* nst    = (const float*)d_in[4];
    const float* kw     = (const float*)d_in[5];
    float*       out    = (float*)d_out;

    hist_kernel<<<NBLK, 256>>>(labels);
    scan_kernel<<<1, 64>>>();
    scatter_kernel<<<NBLK, 32>>>(labels);
    accum_kernel<<<NACC, 256>>>(feats);
    finalize_kernel<<<(NBINS * D2 + 255) / 256, 256>>>(rmean, rvar, nst, out);
    smooth_kernel<<<(NBINS * DCOL + 255) / 256, 256>>>(kw, out);
}